// round 13
// baseline (speedup 1.0000x reference)
#include <cuda_runtime.h>
#include <cuda_fp16.h>
#include <cstdint>

// CIN via mma.sync (base-ISA tensor cores).
// out[r,j] = sum_{h,m} xl[r,h]*x0[r,m]*W[h*32+m,j]; r = b*16+d.
// R13: R12 + precomputed B-ldsm addresses (4 phase bases/chunk) +
//      A-fragment software pipeline (afr computed one ks ahead).

namespace {
constexpr int RTOT = 16384;           // 1024 batches * 16 emb rows
constexpr int NOUT = 128;
constexpr int OUTW = 384;
constexpr int TM   = 64;              // rows per CTA (= 4 batches)
constexpr int NCTA = RTOT / TM;       // 256
constexpr int NTHR = 256;
constexpr int KC   = 128;             // K per chunk
constexpr int CHUNK_BYTES = 128 * KC * 2;   // 32768

// SMEM layout (bytes)
constexpr int OFF_B    = 0;                        // 2 stages x 32768
constexpr int OFF_X0   = 65536;                    // float[64][33] = 8448
constexpr int OFF_BIAS = 73984;                    // 512
constexpr int OFF_XL   = 74496;                    // 2 stages x 1024 (float[4][64])
constexpr int OFF_MBAR = 76544;                    // 2 x 8B
constexpr int SMEM_TOTAL = 76560;
}

// device-global scratch (allocation-free rule)
// g_Wt: per layer, chunk-major pre-swizzled byte image:
//   byte off = c*32768 + (kk>>6)*16384 + j*128 + (((kk&63)*2) ^ ((j&7)<<4))
__device__ __align__(128) __half g_Wt[128 * (1024 + 4096 + 4096)];
__device__ __align__(16) float  g_xlA[RTOT * NOUT];  // transposed [col][row]
__device__ __align__(16) float  g_xlB[RTOT * NOUT];

// ---------------- helpers ----------------
__device__ __forceinline__ uint32_t smem_u32(const void* p) {
    uint32_t a;
    asm("{ .reg .u64 t; cvta.to.shared.u64 t, %1; cvt.u32.u64 %0, t; }" : "=r"(a) : "l"(p));
    return a;
}
__device__ __forceinline__ void ldsm4(uint32_t* r, uint32_t addr) {
    asm volatile("ldmatrix.sync.aligned.m8n8.x4.shared.b16 {%0,%1,%2,%3}, [%4];"
                 : "=r"(r[0]), "=r"(r[1]), "=r"(r[2]), "=r"(r[3]) : "r"(addr));
}
__device__ __forceinline__ void mma16816(float* c, const uint32_t* a, const uint32_t* b) {
    asm volatile("mma.sync.aligned.m16n8k16.row.col.f32.f16.f16.f32 "
                 "{%0,%1,%2,%3}, {%4,%5,%6,%7}, {%8,%9}, {%0,%1,%2,%3};"
                 : "+f"(c[0]), "+f"(c[1]), "+f"(c[2]), "+f"(c[3])
                 : "r"(a[0]), "r"(a[1]), "r"(a[2]), "r"(a[3]), "r"(b[0]), "r"(b[1]));
}
__device__ __forceinline__ uint32_t h2u(__half2 h) {
    return *reinterpret_cast<uint32_t*>(&h);
}
#define MBAR_INIT(mb, n) \
    asm volatile("mbarrier.init.shared.b64 [%0], %1;" :: "r"((uint32_t)(mb)), "r"((uint32_t)(n)) : "memory")
#define MBAR_EXPECT_TX(mb, tx) \
    asm volatile("mbarrier.arrive.expect_tx.shared.b64 _, [%0], %1;" :: "r"((uint32_t)(mb)), "r"((uint32_t)(tx)) : "memory")
#define MBAR_WAIT(mb, ph) \
    asm volatile("{\n\t.reg .pred p;\n\t" \
        "WL_%=:\n\t" \
        "mbarrier.try_wait.parity.shared.b64 p, [%0], %1;\n\t" \
        "@!p bra WL_%=;\n\t}" :: "r"((uint32_t)(mb)), "r"((uint32_t)(ph)) : "memory")
#define BULK_CP(dst, src, bytes, mb) \
    asm volatile("cp.async.bulk.shared::cta.global.mbarrier::complete_tx::bytes [%0], [%1], %2, [%3];" \
                 :: "r"((uint32_t)(dst)), "l"(src), "r"((uint32_t)(bytes)), "r"((uint32_t)(mb)) : "memory")

// ---------------- W -> chunk-major pre-swizzled fp16 image (all layers) ----
// blocks 0..31 -> layer0, 32..159 -> layer1, 160..287 -> layer2
__global__ void wprep_all(const float* __restrict__ W0,
                          const float* __restrict__ W1,
                          const float* __restrict__ W2) {
    const int b = blockIdx.x;
    const float* W;
    char* Wt;
    int kb;
    if (b < 32)       { W = W0; Wt = reinterpret_cast<char*>(g_Wt);          kb = b; }
    else if (b < 160) { W = W1; Wt = reinterpret_cast<char*>(g_Wt + 131072); kb = b - 32; }
    else              { W = W2; Wt = reinterpret_cast<char*>(g_Wt + 655360); kb = b - 160; }

    __shared__ float s[32][129];
    const int k0 = kb * 32;
    const int t  = threadIdx.x;
#pragma unroll
    for (int i = 0; i < 16; i++) {
        int idx = t + i * 256;
        int kk = idx >> 7, j = idx & 127;
        s[kk][j] = W[(size_t)(k0 + kk) * 128 + j];
    }
    __syncthreads();
    const int j = t >> 1, hb = t & 1;
    const int c = k0 >> 7;
#pragma unroll
    for (int r = 0; r < 2; r++) {
        uint32_t w[4];
        const int kk = (k0 & 127) + hb * 16 + r * 8;
#pragma unroll
        for (int e = 0; e < 4; e++) {
            int kl = hb * 16 + r * 8 + e * 2;
            __half2 h2 = __floats2half2_rn(s[kl][j], s[kl + 1][j]);
            w[e] = *reinterpret_cast<uint32_t*>(&h2);
        }
        size_t off = (size_t)c * 32768 + (kk >> 6) * 16384 + j * 128
                   + (((uint32_t)(kk & 63) * 2) ^ ((uint32_t)(j & 7) << 4));
        *reinterpret_cast<uint4*>(Wt + off) = make_uint4(w[0], w[1], w[2], w[3]);
    }
}

// ---------------- main layer kernel ----------------
template <int LAYER>
__global__ __launch_bounds__(NTHR, 2)
void cin_mma(const float* __restrict__ inputs,
             const float* __restrict__ bias,
             float* __restrict__ out)
{
    constexpr int  K    = (LAYER == 0) ? 1024 : 4096;
    constexpr int  WOFF = (LAYER == 0) ? 0 : (LAYER == 1 ? 131072 : 655360);
    constexpr int  NC   = K / KC;          // 8 / 32 chunks
    constexpr bool RELU = (LAYER < 2);
    constexpr bool WXL  = (LAYER < 2);

    extern __shared__ char smem[];
    const uint32_t sb = smem_u32(smem);

    const int tid  = threadIdx.x;
    const int wid  = tid >> 5;
    const int lane = tid & 31;
    const int blk  = blockIdx.x;
    const int R0   = blk * TM;

    const char*  Wt     = reinterpret_cast<const char*>(g_Wt + WOFF);
    const float* xl_in  = (LAYER == 2) ? g_xlB : g_xlA;
    float*       xl_out = (LAYER == 0) ? g_xlA : g_xlB;

    // ---- mbarrier init + first B bulk copy ----
    if (tid == 0) {
        MBAR_INIT(sb + OFF_MBAR + 0, 1);
        MBAR_INIT(sb + OFF_MBAR + 8, 1);
    }
    __syncthreads();
    if (tid == 0) {
        MBAR_EXPECT_TX(sb + OFF_MBAR + 0, CHUNK_BYTES);
        BULK_CP(sb + OFF_B, Wt, CHUNK_BYTES, sb + OFF_MBAR + 0);
    }

    // ---- x0 tile (4 batches, contiguous 2048 floats) + bias -> SMEM ----
    {
        const float* src = inputs + (size_t)blk * 2048;
        float* x0sw = reinterpret_cast<float*>(smem + OFF_X0);
#pragma unroll
        for (int i = 0; i < 8; i++) {
            int idx = tid + i * NTHR;
            int bb = idx >> 9, m = (idx >> 4) & 31, d = idx & 15;
            x0sw[(bb * 16 + d) * 33 + m] = src[idx];
        }
        if (tid < 128) reinterpret_cast<float*>(smem + OFF_BIAS)[tid] = bias[tid];
    }

    // ---- xl slice prologue (layers > 0): stage0 + prefetch chunk1 ----
    float* xls = reinterpret_cast<float*>(smem + OFF_XL);   // [2][4][64]
    const int xh = tid >> 6, xr = tid & 63;
    float xlv = 0.f;
    if (LAYER > 0) {
        xls[tid] = __ldg(&xl_in[(size_t)xh * RTOT + R0 + xr]);      // chunk 0
        if (NC > 1) xlv = __ldg(&xl_in[(size_t)(4 + xh) * RTOT + R0 + xr]);
    }
    __syncthreads();   // x0s, bias, xl stage0 visible

    // ---- per-thread x0 fragment registers ----
    const int mg = wid >> 2, ng = wid & 3;
    const int rlow = lane >> 2, c0 = (lane & 3) * 2;
    const int g = lane >> 3;
    const float* x0s = reinterpret_cast<const float*>(smem + OFF_X0);
    __half2 x0p[4][4];
    int rowv[4];
#pragma unroll
    for (int rr = 0; rr < 4; rr++) {
        const int mt = rr >> 1, s = rr & 1;
        const int row = mg * 32 + mt * 16 + rlow + s * 8;
        rowv[rr] = row;
#pragma unroll
        for (int j = 0; j < 4; j++)
            x0p[rr][j] = __floats2half2_rn(x0s[row * 33 + c0 + 8 * j],
                                           x0s[row * 33 + c0 + 8 * j + 1]);
    }

    // ---- accumulators: warp tile 32(M) x 32(N); warps = 2M x 4N ----
    float acc[2][4][4];
#pragma unroll
    for (int mt = 0; mt < 2; mt++)
#pragma unroll
        for (int nt = 0; nt < 4; nt++)
#pragma unroll
            for (int e = 0; e < 4; e++) acc[mt][nt][e] = 0.f;

    // B ldsm fixed per-thread row offsets (swizzle bits identical for br+16)
    const int br0 = ng * 32 + (g >> 1) * 8 + (lane & 7);
    const uint32_t broff = (uint32_t)br0 * 128 + (((uint32_t)((g & 1) * 8) * 2) ^ ((br0 & 7) << 4));
    // phase p (=ks&3) adds (p*16*2)=32*p XOR'd? No: bk&63 = p*16+(g&1)*8; (bk&63)*2
    // varies linearly: ((p*16 + (g&1)*8)*2) ^ sw = p*32 + ((g&1)*16 ^ sw) since p*32
    // doesn't intersect the XOR bits? p*32 has bits >=5; sw=(br&7)<<4 occupies bits 4..6.
    // bit 5,6 can collide -> keep full recompute per phase, but hoisted out of ks loop.

    // ================= main K loop =================
    for (int c = 0; c < NC; c++) {
        const int sA = c & 1;

        MBAR_WAIT(sb + OFF_MBAR + 8 * sA, (c >> 1) & 1);  // B(c) landed
        __syncthreads();   // stage sA^1 consumed (c-1); xl stage (c&1) visible

        if (c + 1 < NC) {
            if (tid == 0) {
                MBAR_EXPECT_TX(sb + OFF_MBAR + 8 * (sA ^ 1), CHUNK_BYTES);
                BULK_CP(sb + OFF_B + (sA ^ 1) * 32768,
                        Wt + (size_t)(c + 1) * CHUNK_BYTES,
                        CHUNK_BYTES, sb + OFF_MBAR + 8 * (sA ^ 1));
            }
            if (LAYER > 0) {
                xls[((c + 1) & 1) * 256 + tid] = xlv;     // stage for c+1
                if (c + 2 < NC)
                    xlv = __ldg(&xl_in[(size_t)((c + 2) * 4 + xh) * RTOT + R0 + xr]);
            }
        }

        // ---- xl broadcast regs for this chunk: 4 rows x 4 h ----
        __half2 xl2[4][4];
#pragma unroll
        for (int rr = 0; rr < 4; rr++) {
#pragma unroll
            for (int hh = 0; hh < 4; hh++) {
                float v = (LAYER == 0)
                    ? x0s[rowv[rr] * 33 + c * 4 + hh]
                    : xls[(c & 1) * 256 + hh * 64 + rowv[rr]];
                xl2[rr][hh] = __half2half2(__float2half_rn(v));
            }
        }

        // ---- precompute 4 phase base addresses (br0 tile; br1 = +2048) ----
        const uint32_t bbase = sb + OFF_B + sA * 32768;
        uint32_t ba[4];
#pragma unroll
        for (int ph = 0; ph < 4; ph++) {
            const int bk = ph * 16 + (g & 1) * 8;
            ba[ph] = bbase + (uint32_t)br0 * 128
                   + (((uint32_t)(bk & 63) * 2) ^ ((br0 & 7) << 4));
        }

        // ---- A-fragment generator (8 HMUL2) ----
        auto genA = [&](uint32_t a[2][4], int ks) {
            const int hh = ks >> 1;
            const int jb = (ks & 1) * 2;
#pragma unroll
            for (int mt = 0; mt < 2; mt++) {
                a[mt][0] = h2u(__hmul2(x0p[mt * 2 + 0][jb],     xl2[mt * 2 + 0][hh]));
                a[mt][1] = h2u(__hmul2(x0p[mt * 2 + 1][jb],     xl2[mt * 2 + 1][hh]));
                a[mt][2] = h2u(__hmul2(x0p[mt * 2 + 0][jb + 1], xl2[mt * 2 + 0][hh]));
                a[mt][3] = h2u(__hmul2(x0p[mt * 2 + 1][jb + 1], xl2[mt * 2 + 1][hh]));
            }
        };

        // ---- compute chunk c: 8 k16 steps; B frags AND A frags pipelined ----
        uint32_t bcur[8], bnxt[8];
        uint32_t acur[2][4], anxt[2][4];
        ldsm4(bcur,     ba[0]);
        ldsm4(bcur + 4, ba[0] + 2048);
        genA(acur, 0);
#pragma unroll
        for (int ks = 0; ks < 8; ks++) {
            if (ks < 7) {                          // prefetch ks+1 before mma
                const uint32_t addr = ba[(ks + 1) & 3] + ((ks + 1) >> 2) * 16384;
                ldsm4(bnxt,     addr);
                ldsm4(bnxt + 4, addr + 2048);
                genA(anxt, ks + 1);
            }
#pragma unroll
            for (int mt = 0; mt < 2; mt++)
#pragma unroll
                for (int nt = 0; nt < 4; nt++)
                    mma16816(acc[mt][nt], acur[mt], bcur + nt * 2);
#pragma unroll
            for (int e = 0; e < 8; e++) bcur[e] = bnxt[e];
#pragma unroll
            for (int mt = 0; mt < 2; mt++)
#pragma unroll
                for (int e = 0; e < 4; e++) acur[mt][e] = anxt[mt][e];
        }
    }

    // ================= epilogue (disjoint 32x32 tiles) ======================
    const float* biass = reinterpret_cast<const float*>(smem + OFF_BIAS);
#pragma unroll
    for (int mt = 0; mt < 2; mt++) {
        const int batch = blk * 4 + mg * 2 + mt;     // one m16 tile == one batch
        const int r0 = R0 + mg * 32 + mt * 16 + rlow;
#pragma unroll
        for (int nt = 0; nt < 4; nt++) {
            const int j0 = ng * 32 + nt * 8 + (lane & 3) * 2;
            const float b0 = biass[j0], b1 = biass[j0 + 1];
            float v0 = acc[mt][nt][0] + b0;
            float v1 = acc[mt][nt][1] + b1;
            float v2 = acc[mt][nt][2] + b0;
            float v3 = acc[mt][nt][3] + b1;
            if (RELU) {
                v0 = fmaxf(v0, 0.f); v1 = fmaxf(v1, 0.f);
                v2 = fmaxf(v2, 0.f); v3 = fmaxf(v3, 0.f);
            }
            if (WXL) {
                xl_out[(size_t)j0 * RTOT + r0]           = v0;
                xl_out[(size_t)(j0 + 1) * RTOT + r0]     = v1;
                xl_out[(size_t)j0 * RTOT + r0 + 8]       = v2;
                xl_out[(size_t)(j0 + 1) * RTOT + r0 + 8] = v3;
            }
            float s0 = v0 + v2, s1 = v1 + v3;        // rows r, r+8
            s0 += __shfl_xor_sync(0xffffffffu, s0, 4);
            s1 += __shfl_xor_sync(0xffffffffu, s1, 4);
            s0 += __shfl_xor_sync(0xffffffffu, s0, 8);
            s1 += __shfl_xor_sync(0xffffffffu, s1, 8);
            s0 += __shfl_xor_sync(0xffffffffu, s0, 16);
            s1 += __shfl_xor_sync(0xffffffffu, s1, 16);
            if (lane < 4) {
                float* dst = out + (size_t)batch * OUTW + LAYER * NOUT
                           + ng * 32 + nt * 8 + lane * 2;
                dst[0] = s0;
                dst[1] = s1;
            }
        }
    }
}

// ---------------- host ----------------
extern "C" void kernel_launch(void* const* d_in, const int* in_sizes, int n_in,
                              void* d_out, int out_size)
{
    const float* inputs = (const float*)d_in[0];
    const float* W0     = (const float*)d_in[1];
    const float* b0     = (const float*)d_in[2];
    const float* W1     = (const float*)d_in[3];
    const float* b1     = (const float*)d_in[4];
    const float* W2     = (const float*)d_in[5];
    const float* b2     = (const float*)d_in[6];
    float* out = (float*)d_out;

    cudaFuncSetAttribute(cin_mma<0>, cudaFuncAttributeMaxDynamicSharedMemorySize, SMEM_TOTAL);
    cudaFuncSetAttribute(cin_mma<1>, cudaFuncAttributeMaxDynamicSharedMemorySize, SMEM_TOTAL);
    cudaFuncSetAttribute(cin_mma<2>, cudaFuncAttributeMaxDynamicSharedMemorySize, SMEM_TOTAL);

    wprep_all<<<288, 256>>>(W0, W1, W2);

    cin_mma<0><<<NCTA, NTHR, SMEM_TOTAL>>>(inputs, b0, out);
    cin_mma<1><<<NCTA, NTHR, SMEM_TOTAL>>>(inputs, b1, out);
    cin_mma<2><<<NCTA, NTHR, SMEM_TOTAL>>>(inputs, b2, out);
}

// round 14
// speedup vs baseline: 1.3459x; 1.3459x over previous
#include <cuda_runtime.h>
#include <cuda_fp16.h>
#include <cstdint>

// CIN via mma.sync (base-ISA tensor cores).
// out[r,j] = sum_{h,m} xl[r,h]*x0[r,m]*W[h*32+m,j]; r = b*16+d.
// R14: layers 0/1 = R12 path (unchanged). Layer 2 has no ReLU after it, so
//      sum_d commutes: out2[b] = vec(C2_b) @ W2 + 16*b2, C2_b = xl2_b^T @ x0_b.
//      14x less work for the dominant kernel:
//        l2_gram  -> C2 (fp16 pre-swizzled image, reuses g_xlA)
//        l2_gemm  -> [1024,4096]@[4096,128], 8-way split-K, partials in g_xlB
//        l2_reduce-> sum partials + 16*bias.

namespace {
constexpr int RTOT = 16384;           // 1024 batches * 16 emb rows
constexpr int NOUT = 128;
constexpr int OUTW = 384;
constexpr int TM   = 64;              // rows per CTA (= 4 batches)
constexpr int NCTA = RTOT / TM;       // 256
constexpr int NTHR = 256;
constexpr int KC   = 128;             // K per chunk
constexpr int CHUNK_BYTES = 128 * KC * 2;   // 32768

// SMEM layout for cin_mma (bytes)
constexpr int OFF_B    = 0;                        // 2 stages x 32768
constexpr int OFF_X0   = 65536;                    // float[64][33] = 8448
constexpr int OFF_BIAS = 73984;                    // 512
constexpr int OFF_XL   = 74496;                    // 2 stages x 1024
constexpr int OFF_MBAR = 76544;                    // 2 x 8B
constexpr int SMEM_TOTAL = 76560;

// SMEM layout for l2_gemm (bytes)
constexpr int OFF2_A    = 0;                       // 2 stages x 16384
constexpr int OFF2_B    = 32768;                   // 2 stages x 32768
constexpr int OFF2_MBAR = 98304;                   // 2 x 8B
constexpr int SMEM2_TOTAL = 98320;

// SMEM for l2_gram: float[128*129] xl + float[4096] x0
constexpr int SMEMG_TOTAL = (128 * 129 + 4096) * 4;   // 82432
}

// device-global scratch (allocation-free rule)
// g_Wt: per layer, chunk-major pre-swizzled byte image:
//   byte off = c*32768 + (kk>>6)*16384 + j*128 + (((kk&63)*2) ^ ((j&7)<<4))
__device__ __align__(128) __half g_Wt[128 * (1024 + 4096 + 4096)];
__device__ __align__(128) float  g_xlA[RTOT * NOUT];  // xl1 [col][row]; later C2 image (8MB)
__device__ __align__(128) float  g_xlB[RTOT * NOUT];  // xl2 [col][row]; later split-K partials

// ---------------- helpers ----------------
__device__ __forceinline__ uint32_t smem_u32(const void* p) {
    uint32_t a;
    asm("{ .reg .u64 t; cvta.to.shared.u64 t, %1; cvt.u32.u64 %0, t; }" : "=r"(a) : "l"(p));
    return a;
}
__device__ __forceinline__ void ldsm4(uint32_t* r, uint32_t addr) {
    asm volatile("ldmatrix.sync.aligned.m8n8.x4.shared.b16 {%0,%1,%2,%3}, [%4];"
                 : "=r"(r[0]), "=r"(r[1]), "=r"(r[2]), "=r"(r[3]) : "r"(addr));
}
__device__ __forceinline__ void mma16816(float* c, const uint32_t* a, const uint32_t* b) {
    asm volatile("mma.sync.aligned.m16n8k16.row.col.f32.f16.f16.f32 "
                 "{%0,%1,%2,%3}, {%4,%5,%6,%7}, {%8,%9}, {%0,%1,%2,%3};"
                 : "+f"(c[0]), "+f"(c[1]), "+f"(c[2]), "+f"(c[3])
                 : "r"(a[0]), "r"(a[1]), "r"(a[2]), "r"(a[3]), "r"(b[0]), "r"(b[1]));
}
__device__ __forceinline__ uint32_t h2u(__half2 h) {
    return *reinterpret_cast<uint32_t*>(&h);
}
#define MBAR_INIT(mb, n) \
    asm volatile("mbarrier.init.shared.b64 [%0], %1;" :: "r"((uint32_t)(mb)), "r"((uint32_t)(n)) : "memory")
#define MBAR_EXPECT_TX(mb, tx) \
    asm volatile("mbarrier.arrive.expect_tx.shared.b64 _, [%0], %1;" :: "r"((uint32_t)(mb)), "r"((uint32_t)(tx)) : "memory")
#define MBAR_WAIT(mb, ph) \
    asm volatile("{\n\t.reg .pred p;\n\t" \
        "WL_%=:\n\t" \
        "mbarrier.try_wait.parity.shared.b64 p, [%0], %1;\n\t" \
        "@!p bra WL_%=;\n\t}" :: "r"((uint32_t)(mb)), "r"((uint32_t)(ph)) : "memory")
#define BULK_CP(dst, src, bytes, mb) \
    asm volatile("cp.async.bulk.shared::cta.global.mbarrier::complete_tx::bytes [%0], [%1], %2, [%3];" \
                 :: "r"((uint32_t)(dst)), "l"(src), "r"((uint32_t)(bytes)), "r"((uint32_t)(mb)) : "memory")

// ---------------- W -> chunk-major pre-swizzled fp16 image (all layers) ----
__global__ void wprep_all(const float* __restrict__ W0,
                          const float* __restrict__ W1,
                          const float* __restrict__ W2) {
    const int b = blockIdx.x;
    const float* W;
    char* Wt;
    int kb;
    if (b < 32)       { W = W0; Wt = reinterpret_cast<char*>(g_Wt);          kb = b; }
    else if (b < 160) { W = W1; Wt = reinterpret_cast<char*>(g_Wt + 131072); kb = b - 32; }
    else              { W = W2; Wt = reinterpret_cast<char*>(g_Wt + 655360); kb = b - 160; }

    __shared__ float s[32][129];
    const int k0 = kb * 32;
    const int t  = threadIdx.x;
#pragma unroll
    for (int i = 0; i < 16; i++) {
        int idx = t + i * 256;
        int kk = idx >> 7, j = idx & 127;
        s[kk][j] = W[(size_t)(k0 + kk) * 128 + j];
    }
    __syncthreads();
    const int j = t >> 1, hb = t & 1;
    const int c = k0 >> 7;
#pragma unroll
    for (int r = 0; r < 2; r++) {
        uint32_t w[4];
        const int kk = (k0 & 127) + hb * 16 + r * 8;
#pragma unroll
        for (int e = 0; e < 4; e++) {
            int kl = hb * 16 + r * 8 + e * 2;
            __half2 h2 = __floats2half2_rn(s[kl][j], s[kl + 1][j]);
            w[e] = *reinterpret_cast<uint32_t*>(&h2);
        }
        size_t off = (size_t)c * 32768 + (kk >> 6) * 16384 + j * 128
                   + (((uint32_t)(kk & 63) * 2) ^ ((uint32_t)(j & 7) << 4));
        *reinterpret_cast<uint4*>(Wt + off) = make_uint4(w[0], w[1], w[2], w[3]);
    }
}

// ---------------- layers 0/1 kernel (R12, unchanged) ----------------
template <int LAYER>
__global__ __launch_bounds__(NTHR, 2)
void cin_mma(const float* __restrict__ inputs,
             const float* __restrict__ bias,
             float* __restrict__ out)
{
    constexpr int  K    = (LAYER == 0) ? 1024 : 4096;
    constexpr int  WOFF = (LAYER == 0) ? 0 : 131072;
    constexpr int  NC   = K / KC;

    extern __shared__ char smem[];
    const uint32_t sb = smem_u32(smem);

    const int tid  = threadIdx.x;
    const int wid  = tid >> 5;
    const int lane = tid & 31;
    const int blk  = blockIdx.x;
    const int R0   = blk * TM;

    const char*  Wt     = reinterpret_cast<const char*>(g_Wt + WOFF);
    const float* xl_in  = g_xlA;                       // used only for LAYER==1
    float*       xl_out = (LAYER == 0) ? g_xlA : g_xlB;

    if (tid == 0) {
        MBAR_INIT(sb + OFF_MBAR + 0, 1);
        MBAR_INIT(sb + OFF_MBAR + 8, 1);
    }
    __syncthreads();
    if (tid == 0) {
        MBAR_EXPECT_TX(sb + OFF_MBAR + 0, CHUNK_BYTES);
        BULK_CP(sb + OFF_B, Wt, CHUNK_BYTES, sb + OFF_MBAR + 0);
    }

    {
        const float* src = inputs + (size_t)blk * 2048;
        float* x0sw = reinterpret_cast<float*>(smem + OFF_X0);
#pragma unroll
        for (int i = 0; i < 8; i++) {
            int idx = tid + i * NTHR;
            int bb = idx >> 9, m = (idx >> 4) & 31, d = idx & 15;
            x0sw[(bb * 16 + d) * 33 + m] = src[idx];
        }
        if (tid < 128) reinterpret_cast<float*>(smem + OFF_BIAS)[tid] = bias[tid];
    }

    float* xls = reinterpret_cast<float*>(smem + OFF_XL);
    const int xh = tid >> 6, xr = tid & 63;
    float xlv = 0.f;
    if (LAYER > 0) {
        xls[tid] = __ldg(&xl_in[(size_t)xh * RTOT + R0 + xr]);
        if (NC > 1) xlv = __ldg(&xl_in[(size_t)(4 + xh) * RTOT + R0 + xr]);
    }
    __syncthreads();

    const int mg = wid >> 2, ng = wid & 3;
    const int rlow = lane >> 2, c0 = (lane & 3) * 2;
    const int g = lane >> 3;
    const float* x0s = reinterpret_cast<const float*>(smem + OFF_X0);
    __half2 x0p[4][4];
    int rowv[4];
#pragma unroll
    for (int rr = 0; rr < 4; rr++) {
        const int mt = rr >> 1, s = rr & 1;
        const int row = mg * 32 + mt * 16 + rlow + s * 8;
        rowv[rr] = row;
#pragma unroll
        for (int j = 0; j < 4; j++)
            x0p[rr][j] = __floats2half2_rn(x0s[row * 33 + c0 + 8 * j],
                                           x0s[row * 33 + c0 + 8 * j + 1]);
    }

    float acc[2][4][4];
#pragma unroll
    for (int mt = 0; mt < 2; mt++)
#pragma unroll
        for (int nt = 0; nt < 4; nt++)
#pragma unroll
            for (int e = 0; e < 4; e++) acc[mt][nt][e] = 0.f;

    const int br0 = ng * 32 + (g >> 1) * 8 + (lane & 7);
    const int br1 = br0 + 16;
    auto baddr = [&](uint32_t bbase, int br, int ks) {
        const int bk = ks * 16 + (g & 1) * 8;
        return bbase + (bk >> 6) * 16384 + br * 128
             + (((uint32_t)(bk & 63) * 2) ^ ((br & 7) << 4));
    };

    for (int c = 0; c < NC; c++) {
        const int sA = c & 1;

        MBAR_WAIT(sb + OFF_MBAR + 8 * sA, (c >> 1) & 1);
        __syncthreads();

        if (c + 1 < NC) {
            if (tid == 0) {
                MBAR_EXPECT_TX(sb + OFF_MBAR + 8 * (sA ^ 1), CHUNK_BYTES);
                BULK_CP(sb + OFF_B + (sA ^ 1) * 32768,
                        Wt + (size_t)(c + 1) * CHUNK_BYTES,
                        CHUNK_BYTES, sb + OFF_MBAR + 8 * (sA ^ 1));
            }
            if (LAYER > 0) {
                xls[((c + 1) & 1) * 256 + tid] = xlv;
                if (c + 2 < NC)
                    xlv = __ldg(&xl_in[(size_t)((c + 2) * 4 + xh) * RTOT + R0 + xr]);
            }
        }

        __half2 xl2[4][4];
#pragma unroll
        for (int rr = 0; rr < 4; rr++) {
#pragma unroll
            for (int hh = 0; hh < 4; hh++) {
                float v = (LAYER == 0)
                    ? x0s[rowv[rr] * 33 + c * 4 + hh]
                    : xls[(c & 1) * 256 + hh * 64 + rowv[rr]];
                xl2[rr][hh] = __half2half2(__float2half_rn(v));
            }
        }

        const uint32_t bbase = sb + OFF_B + sA * 32768;
        uint32_t bcur[8], bnxt[8];
        ldsm4(bcur,     baddr(bbase, br0, 0));
        ldsm4(bcur + 4, baddr(bbase, br1, 0));
#pragma unroll
        for (int ks = 0; ks < 8; ks++) {
            if (ks < 7) {
                ldsm4(bnxt,     baddr(bbase, br0, ks + 1));
                ldsm4(bnxt + 4, baddr(bbase, br1, ks + 1));
            }
            const int hh = ks >> 1;
            const int jb = (ks & 1) * 2;
            uint32_t afr[2][4];
#pragma unroll
            for (int mt = 0; mt < 2; mt++) {
                afr[mt][0] = h2u(__hmul2(x0p[mt * 2 + 0][jb],     xl2[mt * 2 + 0][hh]));
                afr[mt][1] = h2u(__hmul2(x0p[mt * 2 + 1][jb],     xl2[mt * 2 + 1][hh]));
                afr[mt][2] = h2u(__hmul2(x0p[mt * 2 + 0][jb + 1], xl2[mt * 2 + 0][hh]));
                afr[mt][3] = h2u(__hmul2(x0p[mt * 2 + 1][jb + 1], xl2[mt * 2 + 1][hh]));
            }
#pragma unroll
            for (int mt = 0; mt < 2; mt++)
#pragma unroll
                for (int nt = 0; nt < 4; nt++)
                    mma16816(acc[mt][nt], afr[mt], bcur + nt * 2);
#pragma unroll
            for (int e = 0; e < 8; e++) bcur[e] = bnxt[e];
        }
    }

    // epilogue: bias + relu (both layers 0/1), write xl, d-reduce to out
    const float* biass = reinterpret_cast<const float*>(smem + OFF_BIAS);
#pragma unroll
    for (int mt = 0; mt < 2; mt++) {
        const int batch = blk * 4 + mg * 2 + mt;
        const int r0 = R0 + mg * 32 + mt * 16 + rlow;
#pragma unroll
        for (int nt = 0; nt < 4; nt++) {
            const int j0 = ng * 32 + nt * 8 + (lane & 3) * 2;
            const float b0 = biass[j0], b1 = biass[j0 + 1];
            float v0 = fmaxf(acc[mt][nt][0] + b0, 0.f);
            float v1 = fmaxf(acc[mt][nt][1] + b1, 0.f);
            float v2 = fmaxf(acc[mt][nt][2] + b0, 0.f);
            float v3 = fmaxf(acc[mt][nt][3] + b1, 0.f);
            xl_out[(size_t)j0 * RTOT + r0]           = v0;
            xl_out[(size_t)(j0 + 1) * RTOT + r0]     = v1;
            xl_out[(size_t)j0 * RTOT + r0 + 8]       = v2;
            xl_out[(size_t)(j0 + 1) * RTOT + r0 + 8] = v3;
            float s0 = v0 + v2, s1 = v1 + v3;
            s0 += __shfl_xor_sync(0xffffffffu, s0, 4);
            s1 += __shfl_xor_sync(0xffffffffu, s1, 4);
            s0 += __shfl_xor_sync(0xffffffffu, s0, 8);
            s1 += __shfl_xor_sync(0xffffffffu, s1, 8);
            s0 += __shfl_xor_sync(0xffffffffu, s0, 16);
            s1 += __shfl_xor_sync(0xffffffffu, s1, 16);
            if (lane < 4) {
                float* dst = out + (size_t)batch * OUTW + LAYER * NOUT
                           + ng * 32 + nt * 8 + lane * 2;
                dst[0] = s0;
                dst[1] = s1;
            }
        }
    }
}

// ---------------- l2_gram: C2_b = xl2_b^T @ x0_b -> fp16 swizzled image ----
// C2 image (reuses g_xlA): per (mtile=b>>6, chunk c=k>>7):
//   byte off = mtile*524288 + c*16384 + (kk>>6)*8192 + (b&63)*128
//            + (((kk&63)*2) ^ (((b&63)&7)<<4)),  kk = k & 127, k = h*32+m
__global__ __launch_bounds__(256, 1)
void l2_gram(const float* __restrict__ inputs)
{
    extern __shared__ float smf[];
    float* xls = smf;                    // [128 h][129] padded
    float* x0s = smf + 128 * 129;        // [8 bb][16 d][32 m]
    const int tid = threadIdx.x;
    const int blk = blockIdx.x;          // 8 batches
    const int R0  = blk * 128;

    // load xl2 block (coalesced f4 over rows), scalar STS into padded layout
#pragma unroll
    for (int i = 0; i < 16; i++) {
        int idx = tid + i * 256;         // 4096 float4s
        int h = idx >> 5, q = idx & 31;
        float4 v = *reinterpret_cast<const float4*>(&g_xlB[(size_t)h * RTOT + R0 + q * 4]);
        float* dst = xls + h * 129 + q * 4;
        dst[0] = v.x; dst[1] = v.y; dst[2] = v.z; dst[3] = v.w;
    }
    // load x0 (transpose m/d on the fly)
    {
        const float* src = inputs + (size_t)blk * 4096;
#pragma unroll
        for (int i = 0; i < 16; i++) {
            int idx = tid + i * 256;
            int bb = idx >> 9, m = (idx >> 4) & 31, d = idx & 15;
            x0s[bb * 512 + d * 32 + m] = src[idx];
        }
    }
    __syncthreads();

    char* c2img = reinterpret_cast<char*>(g_xlA);
#pragma unroll
    for (int p = 0; p < 4; p++) {
        const int pid = tid + p * 256;
        const int bb = pid >> 7, h = pid & 127;
        const float* xr = xls + h * 129 + bb * 16;
        float acc[32];
#pragma unroll
        for (int m = 0; m < 32; m++) acc[m] = 0.f;
#pragma unroll
        for (int d = 0; d < 16; d++) {
            const float xv = xr[d];
            const float4* x4 = reinterpret_cast<const float4*>(x0s + bb * 512 + d * 32);
#pragma unroll
            for (int m4 = 0; m4 < 8; m4++) {
                float4 t = x4[m4];
                acc[m4 * 4 + 0] += xv * t.x;
                acc[m4 * 4 + 1] += xv * t.y;
                acc[m4 * 4 + 2] += xv * t.z;
                acc[m4 * 4 + 3] += xv * t.w;
            }
        }
        // store 32 fp16 values into the swizzled image
        const int b = blk * 8 + bb;
        const int mtile = b >> 6, rowl = b & 63;
        const size_t base = (size_t)mtile * 524288 + (size_t)(h >> 2) * 16384
                          + (size_t)((h >> 1) & 1) * 8192 + (size_t)rowl * 128;
        const uint32_t sw = (uint32_t)(rowl & 7) << 4;
#pragma unroll
        for (int g16 = 0; g16 < 4; g16++) {
            uint32_t w[4];
#pragma unroll
            for (int e = 0; e < 4; e++) {
                __half2 h2 = __floats2half2_rn(acc[g16 * 8 + e * 2], acc[g16 * 8 + e * 2 + 1]);
                w[e] = h2u(h2);
            }
            const uint32_t off = ((uint32_t)((h & 1) * 64 + g16 * 16)) ^ sw;
            *reinterpret_cast<uint4*>(c2img + base + off) = make_uint4(w[0], w[1], w[2], w[3]);
        }
    }
}

// ---------------- l2_gemm: [1024,4096]@[4096,128], 8-way split-K -----------
__global__ __launch_bounds__(256, 2)
void l2_gemm()
{
    extern __shared__ char smem[];
    const uint32_t sb = smem_u32(smem);
    const int tid  = threadIdx.x;
    const int wid  = tid >> 5;
    const int lane = tid & 31;
    const int mtile = blockIdx.x >> 3;   // 0..15
    const int kg    = blockIdx.x & 7;    // 0..7 (4 chunks each)

    const char* Asrc = reinterpret_cast<const char*>(g_xlA)
                     + (size_t)mtile * 524288 + (size_t)kg * 4 * 16384;
    const char* Bsrc = reinterpret_cast<const char*>(g_Wt + 655360)
                     + (size_t)kg * 4 * 32768;

    if (tid == 0) {
        MBAR_INIT(sb + OFF2_MBAR + 0, 1);
        MBAR_INIT(sb + OFF2_MBAR + 8, 1);
    }
    __syncthreads();
    if (tid == 0) {
        MBAR_EXPECT_TX(sb + OFF2_MBAR + 0, 49152);
        BULK_CP(sb + OFF2_A, Asrc, 16384, sb + OFF2_MBAR + 0);
        BULK_CP(sb + OFF2_B, Bsrc, 32768, sb + OFF2_MBAR + 0);
    }

    const int mg = wid >> 2, ng = wid & 3;
    const int rlow = lane >> 2;
    const int g = lane >> 3;

    float acc[2][4][4];
#pragma unroll
    for (int mt = 0; mt < 2; mt++)
#pragma unroll
        for (int nt = 0; nt < 4; nt++)
#pragma unroll
            for (int e = 0; e < 4; e++) acc[mt][nt][e] = 0.f;

    for (int i = 0; i < 4; i++) {
        const int s = i & 1;
        MBAR_WAIT(sb + OFF2_MBAR + 8 * s, (i >> 1) & 1);
        __syncthreads();
        if (i + 1 < 4 && tid == 0) {
            MBAR_EXPECT_TX(sb + OFF2_MBAR + 8 * (s ^ 1), 49152);
            BULK_CP(sb + OFF2_A + (s ^ 1) * 16384, Asrc + (size_t)(i + 1) * 16384,
                    16384, sb + OFF2_MBAR + 8 * (s ^ 1));
            BULK_CP(sb + OFF2_B + (s ^ 1) * 32768, Bsrc + (size_t)(i + 1) * 32768,
                    32768, sb + OFF2_MBAR + 8 * (s ^ 1));
        }
        const uint32_t abase = sb + OFF2_A + s * 16384;
        const uint32_t bbase = sb + OFF2_B + s * 32768;
#pragma unroll
        for (int ks = 0; ks < 8; ks++) {
            const int k0 = ks * 16;
            uint32_t afr[2][4];
#pragma unroll
            for (int mt = 0; mt < 2; mt++) {
                const int ar = mg * 32 + mt * 16 + (g & 1) * 8 + (lane & 7);
                const int ak = k0 + (g >> 1) * 8;
                ldsm4(afr[mt], abase + (ak >> 6) * 8192 + ar * 128
                               + (((uint32_t)(ak & 63) * 2) ^ ((ar & 7) << 4)));
            }
            uint32_t bfr[4][2];
#pragma unroll
            for (int bt = 0; bt < 2; bt++) {
                const int br = ng * 32 + bt * 16 + (g >> 1) * 8 + (lane & 7);
                const int bk = k0 + (g & 1) * 8;
                uint32_t r[4];
                ldsm4(r, bbase + (bk >> 6) * 16384 + br * 128
                         + (((uint32_t)(bk & 63) * 2) ^ ((br & 7) << 4)));
                bfr[bt * 2][0] = r[0]; bfr[bt * 2][1] = r[1];
                bfr[bt * 2 + 1][0] = r[2]; bfr[bt * 2 + 1][1] = r[3];
            }
#pragma unroll
            for (int mt = 0; mt < 2; mt++)
#pragma unroll
                for (int nt = 0; nt < 4; nt++)
                    mma16816(acc[mt][nt], afr[mt], bfr[nt]);
        }
    }

    // write split-K partials (fp32) into g_xlB: [kg][1024 b][128 j]
    float* part = g_xlB + (size_t)kg * 131072;
#pragma unroll
    for (int mt = 0; mt < 2; mt++) {
        const int b = mtile * 64 + mg * 32 + mt * 16 + rlow;
#pragma unroll
        for (int nt = 0; nt < 4; nt++) {
            const int j0 = ng * 32 + nt * 8 + (lane & 3) * 2;
            *reinterpret_cast<float2*>(&part[(size_t)b * 128 + j0]) =
                make_float2(acc[mt][nt][0], acc[mt][nt][1]);
            *reinterpret_cast<float2*>(&part[(size_t)(b + 8) * 128 + j0]) =
                make_float2(acc[mt][nt][2], acc[mt][nt][3]);
        }
    }
}

// ---------------- l2_reduce: out2 = sum_kg partial + 16*bias ---------------
__global__ void l2_reduce(const float* __restrict__ b2, float* __restrict__ out)
{
    const int idx = blockIdx.x * 256 + threadIdx.x;   // 32768 float4 slots
    const int b = idx >> 5, q = idx & 31;
    const int jj = q * 4;
    const float4* part = reinterpret_cast<const float4*>(g_xlB);
    float4 s = make_float4(16.f * b2[jj], 16.f * b2[jj + 1],
                           16.f * b2[jj + 2], 16.f * b2[jj + 3]);
#pragma unroll
    for (int kg = 0; kg < 8; kg++) {
        float4 v = part[(size_t)kg * 32768 + (size_t)b * 32 + q];
        s.x += v.x; s.y += v.y; s.z += v.z; s.w += v.w;
    }
    *reinterpret_cast<float4*>(&out[(size_t)b * OUTW + 256 + jj]) = s;
}

// ---------------- host ----------------
extern "C" void kernel_launch(void* const* d_in, const int* in_sizes, int n_in,
                              void* d_out, int out_size)
{
    const float* inputs = (const float*)d_in[0];
    const float* W0     = (const float*)d_in[1];
    const float* b0     = (const float*)d_in[2];
    const float* W1     = (const float*)d_in[3];
    const float* b1     = (const float*)d_in[4];
    const float* W2     = (const float*)d_in[5];
    const float* b2     = (const float*)d_in[6];
    float* out = (float*)d_out;

    cudaFuncSetAttribute(cin_mma<0>, cudaFuncAttributeMaxDynamicSharedMemorySize, SMEM_TOTAL);
    cudaFuncSetAttribute(cin_mma<1>, cudaFuncAttributeMaxDynamicSharedMemorySize, SMEM_TOTAL);
    cudaFuncSetAttribute(l2_gram, cudaFuncAttributeMaxDynamicSharedMemorySize, SMEMG_TOTAL);
    cudaFuncSetAttribute(l2_gemm, cudaFuncAttributeMaxDynamicSharedMemorySize, SMEM2_TOTAL);

    wprep_all<<<288, 256>>>(W0, W1, W2);

    cin_mma<0><<<NCTA, NTHR, SMEM_TOTAL>>>(inputs, b0, out);
    cin_mma<1><<<NCTA, NTHR, SMEM_TOTAL>>>(inputs, b1, out);
    l2_gram<<<128, 256, SMEMG_TOTAL>>>(inputs);
    l2_gemm<<<128, 256, SMEM2_TOTAL>>>();
    l2_reduce<<<128, 256>>>(b2, out);
}

// round 15
// speedup vs baseline: 1.3772x; 1.0232x over previous
#include <cuda_runtime.h>
#include <cuda_fp16.h>
#include <cstdint>

// CIN via mma.sync (base-ISA tensor cores).
// out[r,j] = sum_{h,m} xl[r,h]*x0[r,m]*W[h*32+m,j]; r = b*16+d.
// R15: R14 + Gram fused into cin_mma<1> epilogue (xl2 never leaves the CTA):
//      C2 image -> g_xlB, split-K partials -> g_xlA, l2_gram kernel deleted.

namespace {
constexpr int RTOT = 16384;           // 1024 batches * 16 emb rows
constexpr int NOUT = 128;
constexpr int OUTW = 384;
constexpr int TM   = 64;              // rows per CTA (= 4 batches)
constexpr int NCTA = RTOT / TM;       // 256
constexpr int NTHR = 256;
constexpr int KC   = 128;             // K per chunk
constexpr int CHUNK_BYTES = 128 * KC * 2;   // 32768

// SMEM layout for cin_mma (bytes)
constexpr int OFF_B    = 0;                        // 2 stages x 32768
constexpr int OFF_X0   = 65536;                    // float[64][33] = 8448
constexpr int OFF_BIAS = 73984;                    // 512
constexpr int OFF_XL   = 74496;                    // 2 stages x 1024
constexpr int OFF_MBAR = 76544;                    // 2 x 8B
constexpr int SMEM_TOTAL = 76560;
// layer-1 epilogue reuses [OFF_B..): float[64][129] xl2 stash (33024 B)

// SMEM layout for l2_gemm (bytes)
constexpr int OFF2_A    = 0;                       // 2 stages x 16384
constexpr int OFF2_B    = 32768;                   // 2 stages x 32768
constexpr int OFF2_MBAR = 98304;                   // 2 x 8B
constexpr int SMEM2_TOTAL = 98320;
}

// device-global scratch (allocation-free rule)
// g_Wt: per layer, chunk-major pre-swizzled byte image:
//   byte off = c*32768 + (kk>>6)*16384 + j*128 + (((kk&63)*2) ^ ((j&7)<<4))
__device__ __align__(128) __half g_Wt[128 * (1024 + 4096 + 4096)];
__device__ __align__(128) float  g_xlA[RTOT * NOUT];  // xl1 [col][row]; later split-K partials
__device__ __align__(128) float  g_xlB[RTOT * NOUT];  // C2 fp16 swizzled image (8MB area)

// ---------------- helpers ----------------
__device__ __forceinline__ uint32_t smem_u32(const void* p) {
    uint32_t a;
    asm("{ .reg .u64 t; cvta.to.shared.u64 t, %1; cvt.u32.u64 %0, t; }" : "=r"(a) : "l"(p));
    return a;
}
__device__ __forceinline__ void ldsm4(uint32_t* r, uint32_t addr) {
    asm volatile("ldmatrix.sync.aligned.m8n8.x4.shared.b16 {%0,%1,%2,%3}, [%4];"
                 : "=r"(r[0]), "=r"(r[1]), "=r"(r[2]), "=r"(r[3]) : "r"(addr));
}
__device__ __forceinline__ void mma16816(float* c, const uint32_t* a, const uint32_t* b) {
    asm volatile("mma.sync.aligned.m16n8k16.row.col.f32.f16.f16.f32 "
                 "{%0,%1,%2,%3}, {%4,%5,%6,%7}, {%8,%9}, {%0,%1,%2,%3};"
                 : "+f"(c[0]), "+f"(c[1]), "+f"(c[2]), "+f"(c[3])
                 : "r"(a[0]), "r"(a[1]), "r"(a[2]), "r"(a[3]), "r"(b[0]), "r"(b[1]));
}
__device__ __forceinline__ uint32_t h2u(__half2 h) {
    return *reinterpret_cast<uint32_t*>(&h);
}
#define MBAR_INIT(mb, n) \
    asm volatile("mbarrier.init.shared.b64 [%0], %1;" :: "r"((uint32_t)(mb)), "r"((uint32_t)(n)) : "memory")
#define MBAR_EXPECT_TX(mb, tx) \
    asm volatile("mbarrier.arrive.expect_tx.shared.b64 _, [%0], %1;" :: "r"((uint32_t)(mb)), "r"((uint32_t)(tx)) : "memory")
#define MBAR_WAIT(mb, ph) \
    asm volatile("{\n\t.reg .pred p;\n\t" \
        "WL_%=:\n\t" \
        "mbarrier.try_wait.parity.shared.b64 p, [%0], %1;\n\t" \
        "@!p bra WL_%=;\n\t}" :: "r"((uint32_t)(mb)), "r"((uint32_t)(ph)) : "memory")
#define BULK_CP(dst, src, bytes, mb) \
    asm volatile("cp.async.bulk.shared::cta.global.mbarrier::complete_tx::bytes [%0], [%1], %2, [%3];" \
                 :: "r"((uint32_t)(dst)), "l"(src), "r"((uint32_t)(bytes)), "r"((uint32_t)(mb)) : "memory")

// ---------------- W -> chunk-major pre-swizzled fp16 image (all layers) ----
__global__ void wprep_all(const float* __restrict__ W0,
                          const float* __restrict__ W1,
                          const float* __restrict__ W2) {
    const int b = blockIdx.x;
    const float* W;
    char* Wt;
    int kb;
    if (b < 32)       { W = W0; Wt = reinterpret_cast<char*>(g_Wt);          kb = b; }
    else if (b < 160) { W = W1; Wt = reinterpret_cast<char*>(g_Wt + 131072); kb = b - 32; }
    else              { W = W2; Wt = reinterpret_cast<char*>(g_Wt + 655360); kb = b - 160; }

    __shared__ float s[32][129];
    const int k0 = kb * 32;
    const int t  = threadIdx.x;
#pragma unroll
    for (int i = 0; i < 16; i++) {
        int idx = t + i * 256;
        int kk = idx >> 7, j = idx & 127;
        s[kk][j] = W[(size_t)(k0 + kk) * 128 + j];
    }
    __syncthreads();
    const int j = t >> 1, hb = t & 1;
    const int c = k0 >> 7;
#pragma unroll
    for (int r = 0; r < 2; r++) {
        uint32_t w[4];
        const int kk = (k0 & 127) + hb * 16 + r * 8;
#pragma unroll
        for (int e = 0; e < 4; e++) {
            int kl = hb * 16 + r * 8 + e * 2;
            __half2 h2 = __floats2half2_rn(s[kl][j], s[kl + 1][j]);
            w[e] = *reinterpret_cast<uint32_t*>(&h2);
        }
        size_t off = (size_t)c * 32768 + (kk >> 6) * 16384 + j * 128
                   + (((uint32_t)(kk & 63) * 2) ^ ((uint32_t)(j & 7) << 4));
        *reinterpret_cast<uint4*>(Wt + off) = make_uint4(w[0], w[1], w[2], w[3]);
    }
}

// ---------------- layers 0/1 kernel ----------------
template <int LAYER>
__global__ __launch_bounds__(NTHR, 2)
void cin_mma(const float* __restrict__ inputs,
             const float* __restrict__ bias,
             float* __restrict__ out)
{
    constexpr int  K    = (LAYER == 0) ? 1024 : 4096;
    constexpr int  WOFF = (LAYER == 0) ? 0 : 131072;
    constexpr int  NC   = K / KC;

    extern __shared__ char smem[];
    const uint32_t sb = smem_u32(smem);

    const int tid  = threadIdx.x;
    const int wid  = tid >> 5;
    const int lane = tid & 31;
    const int blk  = blockIdx.x;
    const int R0   = blk * TM;

    const char*  Wt    = reinterpret_cast<const char*>(g_Wt + WOFF);
    const float* xl_in = g_xlA;                       // used only for LAYER==1

    if (tid == 0) {
        MBAR_INIT(sb + OFF_MBAR + 0, 1);
        MBAR_INIT(sb + OFF_MBAR + 8, 1);
    }
    __syncthreads();
    if (tid == 0) {
        MBAR_EXPECT_TX(sb + OFF_MBAR + 0, CHUNK_BYTES);
        BULK_CP(sb + OFF_B, Wt, CHUNK_BYTES, sb + OFF_MBAR + 0);
    }

    {
        const float* src = inputs + (size_t)blk * 2048;
        float* x0sw = reinterpret_cast<float*>(smem + OFF_X0);
#pragma unroll
        for (int i = 0; i < 8; i++) {
            int idx = tid + i * NTHR;
            int bb = idx >> 9, m = (idx >> 4) & 31, d = idx & 15;
            x0sw[(bb * 16 + d) * 33 + m] = src[idx];
        }
        if (tid < 128) reinterpret_cast<float*>(smem + OFF_BIAS)[tid] = bias[tid];
    }

    float* xls = reinterpret_cast<float*>(smem + OFF_XL);
    const int xh = tid >> 6, xr = tid & 63;
    float xlv = 0.f;
    if (LAYER > 0) {
        xls[tid] = __ldg(&xl_in[(size_t)xh * RTOT + R0 + xr]);
        if (NC > 1) xlv = __ldg(&xl_in[(size_t)(4 + xh) * RTOT + R0 + xr]);
    }
    __syncthreads();

    const int mg = wid >> 2, ng = wid & 3;
    const int rlow = lane >> 2, c0 = (lane & 3) * 2;
    const int g = lane >> 3;
    const float* x0s = reinterpret_cast<const float*>(smem + OFF_X0);
    __half2 x0p[4][4];
    int rowv[4];
#pragma unroll
    for (int rr = 0; rr < 4; rr++) {
        const int mt = rr >> 1, s = rr & 1;
        const int row = mg * 32 + mt * 16 + rlow + s * 8;
        rowv[rr] = row;
#pragma unroll
        for (int j = 0; j < 4; j++)
            x0p[rr][j] = __floats2half2_rn(x0s[row * 33 + c0 + 8 * j],
                                           x0s[row * 33 + c0 + 8 * j + 1]);
    }

    float acc[2][4][4];
#pragma unroll
    for (int mt = 0; mt < 2; mt++)
#pragma unroll
        for (int nt = 0; nt < 4; nt++)
#pragma unroll
            for (int e = 0; e < 4; e++) acc[mt][nt][e] = 0.f;

    const int br0 = ng * 32 + (g >> 1) * 8 + (lane & 7);
    const int br1 = br0 + 16;
    auto baddr = [&](uint32_t bbase, int br, int ks) {
        const int bk = ks * 16 + (g & 1) * 8;
        return bbase + (bk >> 6) * 16384 + br * 128
             + (((uint32_t)(bk & 63) * 2) ^ ((br & 7) << 4));
    };

    for (int c = 0; c < NC; c++) {
        const int sA = c & 1;

        MBAR_WAIT(sb + OFF_MBAR + 8 * sA, (c >> 1) & 1);
        __syncthreads();

        if (c + 1 < NC) {
            if (tid == 0) {
                MBAR_EXPECT_TX(sb + OFF_MBAR + 8 * (sA ^ 1), CHUNK_BYTES);
                BULK_CP(sb + OFF_B + (sA ^ 1) * 32768,
                        Wt + (size_t)(c + 1) * CHUNK_BYTES,
                        CHUNK_BYTES, sb + OFF_MBAR + 8 * (sA ^ 1));
            }
            if (LAYER > 0) {
                xls[((c + 1) & 1) * 256 + tid] = xlv;
                if (c + 2 < NC)
                    xlv = __ldg(&xl_in[(size_t)((c + 2) * 4 + xh) * RTOT + R0 + xr]);
            }
        }

        __half2 xl2[4][4];
#pragma unroll
        for (int rr = 0; rr < 4; rr++) {
#pragma unroll
            for (int hh = 0; hh < 4; hh++) {
                float v = (LAYER == 0)
                    ? x0s[rowv[rr] * 33 + c * 4 + hh]
                    : xls[(c & 1) * 256 + hh * 64 + rowv[rr]];
                xl2[rr][hh] = __half2half2(__float2half_rn(v));
            }
        }

        const uint32_t bbase = sb + OFF_B + sA * 32768;
        uint32_t bcur[8], bnxt[8];
        ldsm4(bcur,     baddr(bbase, br0, 0));
        ldsm4(bcur + 4, baddr(bbase, br1, 0));
#pragma unroll
        for (int ks = 0; ks < 8; ks++) {
            if (ks < 7) {
                ldsm4(bnxt,     baddr(bbase, br0, ks + 1));
                ldsm4(bnxt + 4, baddr(bbase, br1, ks + 1));
            }
            const int hh = ks >> 1;
            const int jb = (ks & 1) * 2;
            uint32_t afr[2][4];
#pragma unroll
            for (int mt = 0; mt < 2; mt++) {
                afr[mt][0] = h2u(__hmul2(x0p[mt * 2 + 0][jb],     xl2[mt * 2 + 0][hh]));
                afr[mt][1] = h2u(__hmul2(x0p[mt * 2 + 1][jb],     xl2[mt * 2 + 1][hh]));
                afr[mt][2] = h2u(__hmul2(x0p[mt * 2 + 0][jb + 1], xl2[mt * 2 + 0][hh]));
                afr[mt][3] = h2u(__hmul2(x0p[mt * 2 + 1][jb + 1], xl2[mt * 2 + 1][hh]));
            }
#pragma unroll
            for (int mt = 0; mt < 2; mt++)
#pragma unroll
                for (int nt = 0; nt < 4; nt++)
                    mma16816(acc[mt][nt], afr[mt], bcur + nt * 2);
#pragma unroll
            for (int e = 0; e < 8; e++) bcur[e] = bnxt[e];
        }
    }

    // ======== epilogue: bias + relu; out write; xl1 (L0) / inline gram (L1) ==
    float* xl2s = reinterpret_cast<float*>(smem + OFF_B);  // [64][129] stash (L1)
    if (LAYER == 1) __syncthreads();                       // B stages fully consumed

    const float* biass = reinterpret_cast<const float*>(smem + OFF_BIAS);
#pragma unroll
    for (int mt = 0; mt < 2; mt++) {
        const int batch = blk * 4 + mg * 2 + mt;
        const int rl = mg * 32 + mt * 16 + rlow;           // CTA-local row
#pragma unroll
        for (int nt = 0; nt < 4; nt++) {
            const int j0 = ng * 32 + nt * 8 + (lane & 3) * 2;
            const float b0 = biass[j0], b1 = biass[j0 + 1];
            float v0 = fmaxf(acc[mt][nt][0] + b0, 0.f);
            float v1 = fmaxf(acc[mt][nt][1] + b1, 0.f);
            float v2 = fmaxf(acc[mt][nt][2] + b0, 0.f);
            float v3 = fmaxf(acc[mt][nt][3] + b1, 0.f);
            if (LAYER == 0) {
                g_xlA[(size_t)j0 * RTOT + R0 + rl]           = v0;
                g_xlA[(size_t)(j0 + 1) * RTOT + R0 + rl]     = v1;
                g_xlA[(size_t)j0 * RTOT + R0 + rl + 8]       = v2;
                g_xlA[(size_t)(j0 + 1) * RTOT + R0 + rl + 8] = v3;
            } else {
                xl2s[rl * 129 + j0]           = v0;
                xl2s[rl * 129 + j0 + 1]       = v1;
                xl2s[(rl + 8) * 129 + j0]     = v2;
                xl2s[(rl + 8) * 129 + j0 + 1] = v3;
            }
            float s0 = v0 + v2, s1 = v1 + v3;
            s0 += __shfl_xor_sync(0xffffffffu, s0, 4);
            s1 += __shfl_xor_sync(0xffffffffu, s1, 4);
            s0 += __shfl_xor_sync(0xffffffffu, s0, 8);
            s1 += __shfl_xor_sync(0xffffffffu, s1, 8);
            s0 += __shfl_xor_sync(0xffffffffu, s0, 16);
            s1 += __shfl_xor_sync(0xffffffffu, s1, 16);
            if (lane < 4) {
                float* dst = out + (size_t)batch * OUTW + LAYER * NOUT
                           + ng * 32 + nt * 8 + lane * 2;
                dst[0] = s0;
                dst[1] = s1;
            }
        }
    }

    if (LAYER == 1) {
        __syncthreads();                                   // xl2s complete
        // inline gram: C2_b[h,m] = sum_d xl2[b,d,h] * x0[b,d,m]
        char* img = reinterpret_cast<char*>(g_xlB);
#pragma unroll
        for (int p = 0; p < 2; p++) {
            const int pid = tid + p * 256;                 // 512 (bb,h) pairs
            const int bb = pid >> 7, h = pid & 127;
            float a32[32];
#pragma unroll
            for (int m = 0; m < 32; m++) a32[m] = 0.f;
#pragma unroll
            for (int d = 0; d < 16; d++) {
                const int rl = bb * 16 + d;
                const float xv = xl2s[rl * 129 + h];
                const float* xr = x0s + rl * 33;
#pragma unroll
                for (int m = 0; m < 32; m++) a32[m] += xv * xr[m];
            }
            const int b = blk * 4 + bb;
            const int mtile = b >> 6, rowl = b & 63;
            const size_t base = (size_t)mtile * 524288 + (size_t)(h >> 2) * 16384
                              + (size_t)((h >> 1) & 1) * 8192 + (size_t)rowl * 128;
            const uint32_t sw = (uint32_t)(rowl & 7) << 4;
#pragma unroll
            for (int g16 = 0; g16 < 4; g16++) {
                uint32_t w[4];
#pragma unroll
                for (int e = 0; e < 4; e++) {
                    __half2 h2 = __floats2half2_rn(a32[g16 * 8 + e * 2],
                                                   a32[g16 * 8 + e * 2 + 1]);
                    w[e] = h2u(h2);
                }
                const uint32_t off = ((uint32_t)((h & 1) * 64 + g16 * 16)) ^ sw;
                *reinterpret_cast<uint4*>(img + base + off) = make_uint4(w[0], w[1], w[2], w[3]);
            }
        }
    }
}

// ---------------- l2_gemm: [1024,4096]@[4096,128], 8-way split-K -----------
__global__ __launch_bounds__(256, 2)
void l2_gemm()
{
    extern __shared__ char smem[];
    const uint32_t sb = smem_u32(smem);
    const int tid  = threadIdx.x;
    const int wid  = tid >> 5;
    const int lane = tid & 31;
    const int mtile = blockIdx.x >> 3;   // 0..15
    const int kg    = blockIdx.x & 7;    // 0..7 (4 chunks each)

    const char* Asrc = reinterpret_cast<const char*>(g_xlB)
                     + (size_t)mtile * 524288 + (size_t)kg * 4 * 16384;
    const char* Bsrc = reinterpret_cast<const char*>(g_Wt + 655360)
                     + (size_t)kg * 4 * 32768;

    if (tid == 0) {
        MBAR_INIT(sb + OFF2_MBAR + 0, 1);
        MBAR_INIT(sb + OFF2_MBAR + 8, 1);
    }
    __syncthreads();
    if (tid == 0) {
        MBAR_EXPECT_TX(sb + OFF2_MBAR + 0, 49152);
        BULK_CP(sb + OFF2_A, Asrc, 16384, sb + OFF2_MBAR + 0);
        BULK_CP(sb + OFF2_B, Bsrc, 32768, sb + OFF2_MBAR + 0);
    }

    const int mg = wid >> 2, ng = wid & 3;
    const int rlow = lane >> 2;
    const int g = lane >> 3;

    float acc[2][4][4];
#pragma unroll
    for (int mt = 0; mt < 2; mt++)
#pragma unroll
        for (int nt = 0; nt < 4; nt++)
#pragma unroll
            for (int e = 0; e < 4; e++) acc[mt][nt][e] = 0.f;

    for (int i = 0; i < 4; i++) {
        const int s = i & 1;
        MBAR_WAIT(sb + OFF2_MBAR + 8 * s, (i >> 1) & 1);
        __syncthreads();
        if (i + 1 < 4 && tid == 0) {
            MBAR_EXPECT_TX(sb + OFF2_MBAR + 8 * (s ^ 1), 49152);
            BULK_CP(sb + OFF2_A + (s ^ 1) * 16384, Asrc + (size_t)(i + 1) * 16384,
                    16384, sb + OFF2_MBAR + 8 * (s ^ 1));
            BULK_CP(sb + OFF2_B + (s ^ 1) * 32768, Bsrc + (size_t)(i + 1) * 32768,
                    32768, sb + OFF2_MBAR + 8 * (s ^ 1));
        }
        const uint32_t abase = sb + OFF2_A + s * 16384;
        const uint32_t bbase = sb + OFF2_B + s * 32768;
#pragma unroll
        for (int ks = 0; ks < 8; ks++) {
            const int k0 = ks * 16;
            uint32_t afr[2][4];
#pragma unroll
            for (int mt = 0; mt < 2; mt++) {
                const int ar = mg * 32 + mt * 16 + (g & 1) * 8 + (lane & 7);
                const int ak = k0 + (g >> 1) * 8;
                ldsm4(afr[mt], abase + (ak >> 6) * 8192 + ar * 128
                               + (((uint32_t)(ak & 63) * 2) ^ ((ar & 7) << 4)));
            }
            uint32_t bfr[4][2];
#pragma unroll
            for (int bt = 0; bt < 2; bt++) {
                const int br = ng * 32 + bt * 16 + (g >> 1) * 8 + (lane & 7);
                const int bk = k0 + (g & 1) * 8;
                uint32_t r[4];
                ldsm4(r, bbase + (bk >> 6) * 16384 + br * 128
                         + (((uint32_t)(bk & 63) * 2) ^ ((br & 7) << 4)));
                bfr[bt * 2][0] = r[0]; bfr[bt * 2][1] = r[1];
                bfr[bt * 2 + 1][0] = r[2]; bfr[bt * 2 + 1][1] = r[3];
            }
#pragma unroll
            for (int mt = 0; mt < 2; mt++)
#pragma unroll
                for (int nt = 0; nt < 4; nt++)
                    mma16816(acc[mt][nt], afr[mt], bfr[nt]);
        }
    }

    // write split-K partials (fp32) into g_xlA: [kg][1024 b][128 j]
    float* part = g_xlA + (size_t)kg * 131072;
#pragma unroll
    for (int mt = 0; mt < 2; mt++) {
        const int b = mtile * 64 + mg * 32 + mt * 16 + rlow;
#pragma unroll
        for (int nt = 0; nt < 4; nt++) {
            const int j0 = ng * 32 + nt * 8 + (lane & 3) * 2;
            *reinterpret_cast<float2*>(&part[(size_t)b * 128 + j0]) =
                make_float2(acc[mt][nt][0], acc[mt][nt][1]);
            *reinterpret_cast<float2*>(&part[(size_t)(b + 8) * 128 + j0]) =
                make_float2(acc[mt][nt][2], acc[mt][nt][3]);
        }
    }
}

// ---------------- l2_reduce: out2 = sum_kg partial + 16*bias ---------------
__global__ void l2_reduce(const float* __restrict__ b2, float* __restrict__ out)
{
    const int idx = blockIdx.x * 256 + threadIdx.x;   // 32768 float4 slots
    const int b = idx >> 5, q = idx & 31;
    const int jj = q * 4;
    const float4* part = reinterpret_cast<const float4*>(g_xlA);
    float4 s = make_float4(16.f * b2[jj], 16.f * b2[jj + 1],
                           16.f * b2[jj + 2], 16.f * b2[jj + 3]);
#pragma unroll
    for (int kg = 0; kg < 8; kg++) {
        float4 v = part[(size_t)kg * 32768 + (size_t)b * 32 + q];
        s.x += v.x; s.y += v.y; s.z += v.z; s.w += v.w;
    }
    *reinterpret_cast<float4*>(&out[(size_t)b * OUTW + 256 + jj]) = s;
}

// ---------------- host ----------------
extern "C" void kernel_launch(void* const* d_in, const int* in_sizes, int n_in,
                              void* d_out, int out_size)
{
    const float* inputs = (const float*)d_in[0];
    const float* W0     = (const float*)d_in[1];
    const float* b0     = (const float*)d_in[2];
    const float* W1     = (const float*)d_in[3];
    const float* b1     = (const float*)d_in[4];
    const float* W2     = (const float*)d_in[5];
    const float* b2     = (const float*)d_in[6];
    float* out = (float*)d_out;

    cudaFuncSetAttribute(cin_mma<0>, cudaFuncAttributeMaxDynamicSharedMemorySize, SMEM_TOTAL);
    cudaFuncSetAttribute(cin_mma<1>, cudaFuncAttributeMaxDynamicSharedMemorySize, SMEM_TOTAL);
    cudaFuncSetAttribute(l2_gemm, cudaFuncAttributeMaxDynamicSharedMemorySize, SMEM2_TOTAL);

    wprep_all<<<288, 256>>>(W0, W1, W2);

    cin_mma<0><<<NCTA, NTHR, SMEM_TOTAL>>>(inputs, b0, out);
    cin_mma<1><<<NCTA, NTHR, SMEM_TOTAL>>>(inputs, b1, out);
    l2_gemm<<<128, 256, SMEM2_TOTAL>>>();
    l2_reduce<<<128, 256>>>(b2, out);
}

// round 16
// speedup vs baseline: 1.5264x; 1.1083x over previous
#include <cuda_runtime.h>
#include <cuda_fp16.h>
#include <cstdint>

// CIN via mma.sync (base-ISA tensor cores).
// out[r,j] = sum_{h,m} xl[r,h]*x0[r,m]*W[h*32+m,j]; r = b*16+d.
// R16: layers 0+1 fused in one kernel (row-local dataflow): xl1 lives in an
//      fp16 SMEM stash, unified 40-chunk B pipeline across the layer boundary.
//      Gram fused in epilogue (R15). l2_gemm: 16-way split-K, grid 256,
//      both stages issued up-front.

namespace {
constexpr int RTOT = 16384;           // 1024 batches * 16 emb rows
constexpr int NOUT = 128;
constexpr int OUTW = 384;
constexpr int TM   = 64;              // rows per CTA (= 4 batches)
constexpr int NCTA = RTOT / TM;       // 256
constexpr int NTHR = 256;
constexpr int KC   = 128;             // K per chunk
constexpr int CHUNK_BYTES = 128 * KC * 2;   // 32768
constexpr int NCH_TOT = 8 + 32;       // L0 + L1 chunks

// SMEM layout for cin01 (bytes)
constexpr int OFF_B    = 0;                        // 2 stages x 32768
constexpr int OFF_X0   = 65536;                    // float[64][33] = 8448
constexpr int OFF_BIAS = 73984;                    // 2 x 128 floats = 1024
constexpr int OFF_XLH  = 75008;                    // half[64][132] = 16896
constexpr int OFF_MBAR = 91904;                    // 2 x 8B
constexpr int SMEM_TOTAL = 91920;
// layer-1 epilogue reuses [OFF_B..): float[64][129] xl2 stash (33024 B)

// SMEM layout for l2_gemm (bytes)
constexpr int OFF2_A    = 0;                       // 2 stages x 16384
constexpr int OFF2_B    = 32768;                   // 2 stages x 32768
constexpr int OFF2_MBAR = 98304;                   // 2 x 8B
constexpr int SMEM2_TOTAL = 98320;
}

// device-global scratch (allocation-free rule)
// g_Wt: per layer, chunk-major pre-swizzled byte image:
//   byte off = c*32768 + (kk>>6)*16384 + j*128 + (((kk&63)*2) ^ ((j&7)<<4))
__device__ __align__(128) __half g_Wt[128 * (1024 + 4096 + 4096)];
__device__ __align__(128) float  g_xlA[RTOT * NOUT];  // split-K partials (16 x 1MB)
__device__ __align__(128) float  g_xlB[RTOT * NOUT];  // C2 fp16 swizzled image

// ---------------- helpers ----------------
__device__ __forceinline__ uint32_t smem_u32(const void* p) {
    uint32_t a;
    asm("{ .reg .u64 t; cvta.to.shared.u64 t, %1; cvt.u32.u64 %0, t; }" : "=r"(a) : "l"(p));
    return a;
}
__device__ __forceinline__ void ldsm4(uint32_t* r, uint32_t addr) {
    asm volatile("ldmatrix.sync.aligned.m8n8.x4.shared.b16 {%0,%1,%2,%3}, [%4];"
                 : "=r"(r[0]), "=r"(r[1]), "=r"(r[2]), "=r"(r[3]) : "r"(addr));
}
__device__ __forceinline__ void mma16816(float* c, const uint32_t* a, const uint32_t* b) {
    asm volatile("mma.sync.aligned.m16n8k16.row.col.f32.f16.f16.f32 "
                 "{%0,%1,%2,%3}, {%4,%5,%6,%7}, {%8,%9}, {%0,%1,%2,%3};"
                 : "+f"(c[0]), "+f"(c[1]), "+f"(c[2]), "+f"(c[3])
                 : "r"(a[0]), "r"(a[1]), "r"(a[2]), "r"(a[3]), "r"(b[0]), "r"(b[1]));
}
__device__ __forceinline__ uint32_t h2u(__half2 h) {
    return *reinterpret_cast<uint32_t*>(&h);
}
#define MBAR_INIT(mb, n) \
    asm volatile("mbarrier.init.shared.b64 [%0], %1;" :: "r"((uint32_t)(mb)), "r"((uint32_t)(n)) : "memory")
#define MBAR_EXPECT_TX(mb, tx) \
    asm volatile("mbarrier.arrive.expect_tx.shared.b64 _, [%0], %1;" :: "r"((uint32_t)(mb)), "r"((uint32_t)(tx)) : "memory")
#define MBAR_WAIT(mb, ph) \
    asm volatile("{\n\t.reg .pred p;\n\t" \
        "WL_%=:\n\t" \
        "mbarrier.try_wait.parity.shared.b64 p, [%0], %1;\n\t" \
        "@!p bra WL_%=;\n\t}" :: "r"((uint32_t)(mb)), "r"((uint32_t)(ph)) : "memory")
#define BULK_CP(dst, src, bytes, mb) \
    asm volatile("cp.async.bulk.shared::cta.global.mbarrier::complete_tx::bytes [%0], [%1], %2, [%3];" \
                 :: "r"((uint32_t)(dst)), "l"(src), "r"((uint32_t)(bytes)), "r"((uint32_t)(mb)) : "memory")

// ---------------- W -> chunk-major pre-swizzled fp16 image (all layers) ----
__global__ void wprep_all(const float* __restrict__ W0,
                          const float* __restrict__ W1,
                          const float* __restrict__ W2) {
    const int b = blockIdx.x;
    const float* W;
    char* Wt;
    int kb;
    if (b < 32)       { W = W0; Wt = reinterpret_cast<char*>(g_Wt);          kb = b; }
    else if (b < 160) { W = W1; Wt = reinterpret_cast<char*>(g_Wt + 131072); kb = b - 32; }
    else              { W = W2; Wt = reinterpret_cast<char*>(g_Wt + 655360); kb = b - 160; }

    __shared__ float s[32][129];
    const int k0 = kb * 32;
    const int t  = threadIdx.x;
#pragma unroll
    for (int i = 0; i < 16; i++) {
        int idx = t + i * 256;
        int kk = idx >> 7, j = idx & 127;
        s[kk][j] = W[(size_t)(k0 + kk) * 128 + j];
    }
    __syncthreads();
    const int j = t >> 1, hb = t & 1;
    const int c = k0 >> 7;
#pragma unroll
    for (int r = 0; r < 2; r++) {
        uint32_t w[4];
        const int kk = (k0 & 127) + hb * 16 + r * 8;
#pragma unroll
        for (int e = 0; e < 4; e++) {
            int kl = hb * 16 + r * 8 + e * 2;
            __half2 h2 = __floats2half2_rn(s[kl][j], s[kl + 1][j]);
            w[e] = *reinterpret_cast<uint32_t*>(&h2);
        }
        size_t off = (size_t)c * 32768 + (kk >> 6) * 16384 + j * 128
                   + (((uint32_t)(kk & 63) * 2) ^ ((uint32_t)(j & 7) << 4));
        *reinterpret_cast<uint4*>(Wt + off) = make_uint4(w[0], w[1], w[2], w[3]);
    }
}

// ---------------- fused layers 0+1 kernel ----------------
__global__ __launch_bounds__(NTHR, 2)
void cin01(const float* __restrict__ inputs,
           const float* __restrict__ b0,
           const float* __restrict__ b1,
           float* __restrict__ out)
{
    extern __shared__ char smem[];
    const uint32_t sb = smem_u32(smem);

    const int tid  = threadIdx.x;
    const int wid  = tid >> 5;
    const int lane = tid & 31;
    const int blk  = blockIdx.x;

    const char* Wt0 = reinterpret_cast<const char*>(g_Wt);
    const char* Wt1 = reinterpret_cast<const char*>(g_Wt + 131072);

    auto chunk_src = [&](int i) -> const char* {
        return (i < 8) ? Wt0 + (size_t)i * CHUNK_BYTES
                       : Wt1 + (size_t)(i - 8) * CHUNK_BYTES;
    };
    auto issue = [&](int i) {
        if (tid == 0) {
            MBAR_EXPECT_TX(sb + OFF_MBAR + 8 * (i & 1), CHUNK_BYTES);
            BULK_CP(sb + OFF_B + (i & 1) * 32768, chunk_src(i),
                    CHUNK_BYTES, sb + OFF_MBAR + 8 * (i & 1));
        }
    };

    if (tid == 0) {
        MBAR_INIT(sb + OFF_MBAR + 0, 1);
        MBAR_INIT(sb + OFF_MBAR + 8, 1);
    }
    __syncthreads();
    issue(0);

    // ---- x0 tile (4 batches, contiguous 2048 floats) + both biases ----
    {
        const float* src = inputs + (size_t)blk * 2048;
        float* x0sw = reinterpret_cast<float*>(smem + OFF_X0);
#pragma unroll
        for (int i = 0; i < 8; i++) {
            int idx = tid + i * NTHR;
            int bb = idx >> 9, m = (idx >> 4) & 31, d = idx & 15;
            x0sw[(bb * 16 + d) * 33 + m] = src[idx];
        }
        float* biass = reinterpret_cast<float*>(smem + OFF_BIAS);
        if (tid < 128)      biass[tid] = b0[tid];
        else                biass[tid] = b1[tid - 128];
    }
    __syncthreads();

    // ---- per-thread x0 fragment registers ----
    const int mg = wid >> 2, ng = wid & 3;
    const int rlow = lane >> 2, c0 = (lane & 3) * 2;
    const int g = lane >> 3;
    const float* x0s = reinterpret_cast<const float*>(smem + OFF_X0);
    __half2 x0p[4][4];
    int rowv[4];
#pragma unroll
    for (int rr = 0; rr < 4; rr++) {
        const int mt = rr >> 1, s = rr & 1;
        const int row = mg * 32 + mt * 16 + rlow + s * 8;
        rowv[rr] = row;
#pragma unroll
        for (int j = 0; j < 4; j++)
            x0p[rr][j] = __floats2half2_rn(x0s[row * 33 + c0 + 8 * j],
                                           x0s[row * 33 + c0 + 8 * j + 1]);
    }

    float acc[2][4][4];
#pragma unroll
    for (int mt = 0; mt < 2; mt++)
#pragma unroll
        for (int nt = 0; nt < 4; nt++)
#pragma unroll
            for (int e = 0; e < 4; e++) acc[mt][nt][e] = 0.f;

    const int br0 = ng * 32 + (g >> 1) * 8 + (lane & 7);
    const int br1 = br0 + 16;
    auto baddr = [&](uint32_t bbase, int br, int ks) {
        const int bk = ks * 16 + (g & 1) * 8;
        return bbase + (bk >> 6) * 16384 + br * 128
             + (((uint32_t)(bk & 63) * 2) ^ ((br & 7) << 4));
    };

    // compute one 128-K chunk given xl2 broadcast regs
    auto do_chunk = [&](int i, __half2 xl2[4][4]) {
        const uint32_t bbase = sb + OFF_B + (i & 1) * 32768;
        uint32_t bcur[8], bnxt[8];
        ldsm4(bcur,     baddr(bbase, br0, 0));
        ldsm4(bcur + 4, baddr(bbase, br1, 0));
#pragma unroll
        for (int ks = 0; ks < 8; ks++) {
            if (ks < 7) {
                ldsm4(bnxt,     baddr(bbase, br0, ks + 1));
                ldsm4(bnxt + 4, baddr(bbase, br1, ks + 1));
            }
            const int hh = ks >> 1;
            const int jb = (ks & 1) * 2;
            uint32_t afr[2][4];
#pragma unroll
            for (int mt = 0; mt < 2; mt++) {
                afr[mt][0] = h2u(__hmul2(x0p[mt * 2 + 0][jb],     xl2[mt * 2 + 0][hh]));
                afr[mt][1] = h2u(__hmul2(x0p[mt * 2 + 1][jb],     xl2[mt * 2 + 1][hh]));
                afr[mt][2] = h2u(__hmul2(x0p[mt * 2 + 0][jb + 1], xl2[mt * 2 + 0][hh]));
                afr[mt][3] = h2u(__hmul2(x0p[mt * 2 + 1][jb + 1], xl2[mt * 2 + 1][hh]));
            }
#pragma unroll
            for (int mt = 0; mt < 2; mt++)
#pragma unroll
                for (int nt = 0; nt < 4; nt++)
                    mma16816(acc[mt][nt], afr[mt], bcur + nt * 2);
#pragma unroll
            for (int e = 0; e < 8; e++) bcur[e] = bnxt[e];
        }
    };

    __half* xlh = reinterpret_cast<__half*>(smem + OFF_XLH);   // [64][132]
    const float* biass = reinterpret_cast<const float*>(smem + OFF_BIAS);

    // ================= layer 0: chunks 0..7 =================
    for (int i = 0; i < 8; i++) {
        MBAR_WAIT(sb + OFF_MBAR + 8 * (i & 1), (i >> 1) & 1);
        __syncthreads();
        if (i + 1 < NCH_TOT) issue(i + 1);

        __half2 xl2[4][4];
#pragma unroll
        for (int rr = 0; rr < 4; rr++)
#pragma unroll
            for (int hh = 0; hh < 4; hh++)
                xl2[rr][hh] = __half2half2(__float2half_rn(x0s[rowv[rr] * 33 + i * 4 + hh]));
        do_chunk(i, xl2);
    }

    // ---- layer 0 epilogue: relu -> fp16 stash; d-sum -> out cols [0,128) ----
#pragma unroll
    for (int mt = 0; mt < 2; mt++) {
        const int batch = blk * 4 + mg * 2 + mt;
        const int rl = mg * 32 + mt * 16 + rlow;
#pragma unroll
        for (int nt = 0; nt < 4; nt++) {
            const int j0 = ng * 32 + nt * 8 + (lane & 3) * 2;
            const float bb0 = biass[j0], bb1 = biass[j0 + 1];
            float v0 = fmaxf(acc[mt][nt][0] + bb0, 0.f);
            float v1 = fmaxf(acc[mt][nt][1] + bb1, 0.f);
            float v2 = fmaxf(acc[mt][nt][2] + bb0, 0.f);
            float v3 = fmaxf(acc[mt][nt][3] + bb1, 0.f);
            *reinterpret_cast<__half2*>(&xlh[rl * 132 + j0])       = __floats2half2_rn(v0, v1);
            *reinterpret_cast<__half2*>(&xlh[(rl + 8) * 132 + j0]) = __floats2half2_rn(v2, v3);
            float s0 = v0 + v2, s1 = v1 + v3;
            s0 += __shfl_xor_sync(0xffffffffu, s0, 4);
            s1 += __shfl_xor_sync(0xffffffffu, s1, 4);
            s0 += __shfl_xor_sync(0xffffffffu, s0, 8);
            s1 += __shfl_xor_sync(0xffffffffu, s1, 8);
            s0 += __shfl_xor_sync(0xffffffffu, s0, 16);
            s1 += __shfl_xor_sync(0xffffffffu, s1, 16);
            if (lane < 4) {
                float* dst = out + (size_t)batch * OUTW + ng * 32 + nt * 8 + lane * 2;
                dst[0] = s0;
                dst[1] = s1;
            }
        }
    }
    __syncthreads();   // xlh stash visible to all warps

#pragma unroll
    for (int mt = 0; mt < 2; mt++)
#pragma unroll
        for (int nt = 0; nt < 4; nt++)
#pragma unroll
            for (int e = 0; e < 4; e++) acc[mt][nt][e] = 0.f;

    // ================= layer 1: chunks 8..39 =================
    for (int i = 8; i < NCH_TOT; i++) {
        MBAR_WAIT(sb + OFF_MBAR + 8 * (i & 1), (i >> 1) & 1);
        __syncthreads();
        if (i + 1 < NCH_TOT) issue(i + 1);

        const int c1 = i - 8;
        __half2 xl2[4][4];
#pragma unroll
        for (int rr = 0; rr < 4; rr++)
#pragma unroll
            for (int hh = 0; hh < 4; hh++)
                xl2[rr][hh] = __half2half2(xlh[rowv[rr] * 132 + c1 * 4 + hh]);
        do_chunk(i, xl2);
    }

    // ---- layer 1 epilogue: fp32 stash in OFF_B; out cols [128,256); gram ----
    float* xl2s = reinterpret_cast<float*>(smem + OFF_B);  // [64][129]
    __syncthreads();                                       // B stages consumed
#pragma unroll
    for (int mt = 0; mt < 2; mt++) {
        const int batch = blk * 4 + mg * 2 + mt;
        const int rl = mg * 32 + mt * 16 + rlow;
#pragma unroll
        for (int nt = 0; nt < 4; nt++) {
            const int j0 = ng * 32 + nt * 8 + (lane & 3) * 2;
            const float bb0 = biass[128 + j0], bb1 = biass[128 + j0 + 1];
            float v0 = fmaxf(acc[mt][nt][0] + bb0, 0.f);
            float v1 = fmaxf(acc[mt][nt][1] + bb1, 0.f);
            float v2 = fmaxf(acc[mt][nt][2] + bb0, 0.f);
            float v3 = fmaxf(acc[mt][nt][3] + bb1, 0.f);
            xl2s[rl * 129 + j0]           = v0;
            xl2s[rl * 129 + j0 + 1]       = v1;
            xl2s[(rl + 8) * 129 + j0]     = v2;
            xl2s[(rl + 8) * 129 + j0 + 1] = v3;
            float s0 = v0 + v2, s1 = v1 + v3;
            s0 += __shfl_xor_sync(0xffffffffu, s0, 4);
            s1 += __shfl_xor_sync(0xffffffffu, s1, 4);
            s0 += __shfl_xor_sync(0xffffffffu, s0, 8);
            s1 += __shfl_xor_sync(0xffffffffu, s1, 8);
            s0 += __shfl_xor_sync(0xffffffffu, s0, 16);
            s1 += __shfl_xor_sync(0xffffffffu, s1, 16);
            if (lane < 4) {
                float* dst = out + (size_t)batch * OUTW + 128 + ng * 32 + nt * 8 + lane * 2;
                dst[0] = s0;
                dst[1] = s1;
            }
        }
    }
    __syncthreads();                                   // xl2s complete

    // inline gram: C2_b[h,m] = sum_d xl2[b,d,h] * x0[b,d,m] -> fp16 image
    {
        char* img = reinterpret_cast<char*>(g_xlB);
#pragma unroll
        for (int p = 0; p < 2; p++) {
            const int pid = tid + p * 256;
            const int bb = pid >> 7, h = pid & 127;
            float a32[32];
#pragma unroll
            for (int m = 0; m < 32; m++) a32[m] = 0.f;
#pragma unroll
            for (int d = 0; d < 16; d++) {
                const int rl = bb * 16 + d;
                const float xv = xl2s[rl * 129 + h];
                const float* xr = x0s + rl * 33;
#pragma unroll
                for (int m = 0; m < 32; m++) a32[m] += xv * xr[m];
            }
            const int b = blk * 4 + bb;
            const int mtile = b >> 6, rowl = b & 63;
            const size_t base = (size_t)mtile * 524288 + (size_t)(h >> 2) * 16384
                              + (size_t)((h >> 1) & 1) * 8192 + (size_t)rowl * 128;
            const uint32_t sw = (uint32_t)(rowl & 7) << 4;
#pragma unroll
            for (int g16 = 0; g16 < 4; g16++) {
                uint32_t w[4];
#pragma unroll
                for (int e = 0; e < 4; e++) {
                    __half2 h2 = __floats2half2_rn(a32[g16 * 8 + e * 2],
                                                   a32[g16 * 8 + e * 2 + 1]);
                    w[e] = h2u(h2);
                }
                const uint32_t off = ((uint32_t)((h & 1) * 64 + g16 * 16)) ^ sw;
                *reinterpret_cast<uint4*>(img + base + off) = make_uint4(w[0], w[1], w[2], w[3]);
            }
        }
    }
}

// ---------------- l2_gemm: [1024,4096]@[4096,128], 16-way split-K ----------
__global__ __launch_bounds__(256, 2)
void l2_gemm()
{
    extern __shared__ char smem[];
    const uint32_t sb = smem_u32(smem);
    const int tid  = threadIdx.x;
    const int wid  = tid >> 5;
    const int lane = tid & 31;
    const int mtile = blockIdx.x >> 4;   // 0..15
    const int kg    = blockIdx.x & 15;   // 0..15 (2 chunks each)

    const char* Asrc = reinterpret_cast<const char*>(g_xlB)
                     + (size_t)mtile * 524288 + (size_t)kg * 2 * 16384;
    const char* Bsrc = reinterpret_cast<const char*>(g_Wt + 655360)
                     + (size_t)kg * 2 * 32768;

    if (tid == 0) {
        MBAR_INIT(sb + OFF2_MBAR + 0, 1);
        MBAR_INIT(sb + OFF2_MBAR + 8, 1);
    }
    __syncthreads();
    if (tid == 0) {   // both stages up-front: zero wait-chain
#pragma unroll
        for (int i = 0; i < 2; i++) {
            MBAR_EXPECT_TX(sb + OFF2_MBAR + 8 * i, 49152);
            BULK_CP(sb + OFF2_A + i * 16384, Asrc + (size_t)i * 16384,
                    16384, sb + OFF2_MBAR + 8 * i);
            BULK_CP(sb + OFF2_B + i * 32768, Bsrc + (size_t)i * 32768,
                    32768, sb + OFF2_MBAR + 8 * i);
        }
    }

    const int mg = wid >> 2, ng = wid & 3;
    const int rlow = lane >> 2;
    const int g = lane >> 3;

    float acc[2][4][4];
#pragma unroll
    for (int mt = 0; mt < 2; mt++)
#pragma unroll
        for (int nt = 0; nt < 4; nt++)
#pragma unroll
            for (int e = 0; e < 4; e++) acc[mt][nt][e] = 0.f;

#pragma unroll
    for (int i = 0; i < 2; i++) {
        MBAR_WAIT(sb + OFF2_MBAR + 8 * i, 0);
        const uint32_t abase = sb + OFF2_A + i * 16384;
        const uint32_t bbase = sb + OFF2_B + i * 32768;
#pragma unroll
        for (int ks = 0; ks < 8; ks++) {
            const int k0 = ks * 16;
            uint32_t afr[2][4];
#pragma unroll
            for (int mt = 0; mt < 2; mt++) {
                const int ar = mg * 32 + mt * 16 + (g & 1) * 8 + (lane & 7);
                const int ak = k0 + (g >> 1) * 8;
                ldsm4(afr[mt], abase + (ak >> 6) * 8192 + ar * 128
                               + (((uint32_t)(ak & 63) * 2) ^ ((ar & 7) << 4)));
            }
            uint32_t bfr[4][2];
#pragma unroll
            for (int bt = 0; bt < 2; bt++) {
                const int br = ng * 32 + bt * 16 + (g >> 1) * 8 + (lane & 7);
                const int bk = k0 + (g & 1) * 8;
                uint32_t r[4];
                ldsm4(r, bbase + (bk >> 6) * 16384 + br * 128
                         + (((uint32_t)(bk & 63) * 2) ^ ((br & 7) << 4)));
                bfr[bt * 2][0] = r[0]; bfr[bt * 2][1] = r[1];
                bfr[bt * 2 + 1][0] = r[2]; bfr[bt * 2 + 1][1] = r[3];
            }
#pragma unroll
            for (int mt = 0; mt < 2; mt++)
#pragma unroll
                for (int nt = 0; nt < 4; nt++)
                    mma16816(acc[mt][nt], afr[mt], bfr[nt]);
        }
    }

    // write split-K partials (fp32) into g_xlA: [kg][1024 b][128 j]
    float* part = g_xlA + (size_t)kg * 131072;
#pragma unroll
    for (int mt = 0; mt < 2; mt++) {
        const int b = mtile * 64 + mg * 32 + mt * 16 + rlow;
#pragma unroll
        for (int nt = 0; nt < 4; nt++) {
            const int j0 = ng * 32 + nt * 8 + (lane & 3) * 2;
            *reinterpret_cast<float2*>(&part[(size_t)b * 128 + j0]) =
                make_float2(acc[mt][nt][0], acc[mt][nt][1]);
            *reinterpret_cast<float2*>(&part[(size_t)(b + 8) * 128 + j0]) =
                make_float2(acc[mt][nt][2], acc[mt][nt][3]);
        }
    }
}

// ---------------- l2_reduce: out2 = sum_kg partial + 16*bias ---------------
__global__ void l2_reduce(const float* __restrict__ b2, float* __restrict__ out)
{
    const int idx = blockIdx.x * 256 + threadIdx.x;   // 32768 float4 slots
    const int b = idx >> 5, q = idx & 31;
    const int jj = q * 4;
    const float4* part = reinterpret_cast<const float4*>(g_xlA);
    float4 s = make_float4(16.f * b2[jj], 16.f * b2[jj + 1],
                           16.f * b2[jj + 2], 16.f * b2[jj + 3]);
#pragma unroll
    for (int kg = 0; kg < 16; kg++) {
        float4 v = part[(size_t)kg * 32768 + (size_t)b * 32 + q];
        s.x += v.x; s.y += v.y; s.z += v.z; s.w += v.w;
    }
    *reinterpret_cast<float4*>(&out[(size_t)b * OUTW + 256 + jj]) = s;
}

// ---------------- host ----------------
extern "C" void kernel_launch(void* const* d_in, const int* in_sizes, int n_in,
                              void* d_out, int out_size)
{
    const float* inputs = (const float*)d_in[0];
    const float* W0     = (const float*)d_in[1];
    const float* b0     = (const float*)d_in[2];
    const float* W1     = (const float*)d_in[3];
    const float* b1     = (const float*)d_in[4];
    const float* W2     = (const float*)d_in[5];
    const float* b2     = (const float*)d_in[6];
    float* out = (float*)d_out;

    cudaFuncSetAttribute(cin01,   cudaFuncAttributeMaxDynamicSharedMemorySize, SMEM_TOTAL);
    cudaFuncSetAttribute(l2_gemm, cudaFuncAttributeMaxDynamicSharedMemorySize, SMEM2_TOTAL);

    wprep_all<<<288, 256>>>(W0, W1, W2);

    cin01<<<NCTA, NTHR, SMEM_TOTAL>>>(inputs, b0, b1, out);
    l2_gemm<<<256, 256, SMEM2_TOTAL>>>();
    l2_reduce<<<128, 256>>>(b2, out);
}